// round 14
// baseline (speedup 1.0000x reference)
#include <cuda_runtime.h>
#include <cstdint>
#include <cstddef>

#define B_ 4
#define R_ 256
#define E_ 8192
#define D_ 256
#define NE_ (B_*E_)   /* 32768 edge rows */
#define NR_ (B_*R_)   /* 1024 node rows */
#define CAP_ 1280
#define BUDGET_ 7864

// ---------------- static scratch (no allocs allowed) ----------------
__device__ float g_node[NR_*D_];     // node_feat
__device__ float g_comm[NR_*D_];     // comm_feat
__device__ float g_ef0 [NE_*D_];     // ef0 -> token -> routed
__device__ float g_buf1[NE_*D_];     // lnE  -> h
__device__ float g_edge[NE_*D_];     // edge_feat -> lnH
__device__ int   g_rel [NE_];
__device__ int   g_cnt [16];         // [0]=keep1 total, [1]=keep3 total, [2..9]=rel hist

// ---------------- helpers ----------------
__device__ __forceinline__ float geluf(float x) {
    return 0.5f * x * (1.0f + erff(x * 0.7071067811865476f));
}

// Threefry-2x32, key = (0, 42)  (jax.random.key(42))
__device__ __forceinline__ void threefry42(unsigned& x0, unsigned& x1) {
    const unsigned k0 = 0u, k1 = 42u;
    const unsigned k2 = k0 ^ k1 ^ 0x1BD11BDAu;
    x0 += k0; x1 += k1;
#define TF_RND(r) { x0 += x1; x1 = (x1 << (r)) | (x1 >> (32-(r))); x1 ^= x0; }
    TF_RND(13) TF_RND(15) TF_RND(26) TF_RND(6)   x0 += k1; x1 += k2 + 1u;
    TF_RND(17) TF_RND(29) TF_RND(16) TF_RND(24)  x0 += k2; x1 += k0 + 2u;
    TF_RND(13) TF_RND(15) TF_RND(26) TF_RND(6)   x0 += k0; x1 += k1 + 3u;
    TF_RND(17) TF_RND(29) TF_RND(16) TF_RND(24)  x0 += k1; x1 += k2 + 4u;
    TF_RND(13) TF_RND(15) TF_RND(26) TF_RND(6)   x0 += k2; x1 += k0 + 5u;
#undef TF_RND
}

// fused A loader for the token GEMM (K = 1024 = [edge | src | dst | |dcomm|])
__device__ __forceinline__ float4 loadA4_tok(
    const float* __restrict__ edgef, const float* __restrict__ nodef,
    const float* __restrict__ commf, const int* __restrict__ eidx,
    int grow, int k)
{
    if (k < 256) return *(const float4*)(edgef + (size_t)grow*256 + k);
    int b = grow >> 13, e = grow & 8191;
    int s = eidx[b*2*E_ + e];
    int d = eidx[b*2*E_ + E_ + e];
    int rb = b * R_;
    if (k < 512) return *(const float4*)(nodef + (size_t)(rb+s)*256 + (k-256));
    if (k < 768) return *(const float4*)(nodef + (size_t)(rb+d)*256 + (k-512));
    float4 a = *(const float4*)(commf + (size_t)(rb+s)*256 + (k-768));
    float4 c = *(const float4*)(commf + (size_t)(rb+d)*256 + (k-768));
    return make_float4(fabsf(a.x-c.x), fabsf(a.y-c.y), fabsf(a.z-c.z), fabsf(a.w-c.w));
}

// ---------------- GEMM: out[Nr x 256] = A[Nr x K] @ W[K x 256] (+epilogue) ----------------
// 128x128 block, BK=8, 256 threads, 8x8 per-thread microtile.
// AMODE: 0 = plain row-major A; 1 = fused token loader.
// EPI:   0 = +bias; 1 = gelu(+bias); 2 = res + gelu(+bias)
template<int AMODE, int EPI>
__global__ void __launch_bounds__(256, 2)
gemm_k(const float* __restrict__ A, const float* __restrict__ W,
       const float* __restrict__ bias, const float* __restrict__ res,
       float* __restrict__ out, int K,
       const float* __restrict__ nodef, const float* __restrict__ commf,
       const int* __restrict__ eidx)
{
    __shared__ float As[8][128];
    __shared__ float Bs[8][128];
    const int tid = threadIdx.x;
    const int tx = tid & 15, ty = tid >> 4;
    const int row0 = blockIdx.x * 128;
    const int col0 = blockIdx.y * 128;

    const int arow = tid >> 1;            // 0..127
    const int akk0 = (tid & 1) * 4;       // 0 or 4
    const int bkk  = tid >> 5;            // 0..7
    const int bcol = (tid << 2) & 127;    // 0..124 step 4

    float acc[8][8];
#pragma unroll
    for (int i = 0; i < 8; i++)
#pragma unroll
        for (int j = 0; j < 8; j++) acc[i][j] = 0.f;

    for (int k0 = 0; k0 < K; k0 += 8) {
        float4 av;
        const int grow = row0 + arow;
        if (AMODE == 0) {
            av = *(const float4*)(A + (size_t)grow*K + k0 + akk0);
        } else {
            av = loadA4_tok(A, nodef, commf, eidx, grow, k0 + akk0);
        }
        As[akk0+0][arow] = av.x; As[akk0+1][arow] = av.y;
        As[akk0+2][arow] = av.z; As[akk0+3][arow] = av.w;

        float4 bv = *(const float4*)(W + (size_t)(k0+bkk)*256 + col0 + bcol);
        *(float4*)&Bs[bkk][bcol] = bv;
        __syncthreads();

#pragma unroll
        for (int kk = 0; kk < 8; kk++) {
            float4 a0 = *(float4*)&As[kk][ty*8];
            float4 a1 = *(float4*)&As[kk][ty*8+4];
            float4 b0 = *(float4*)&Bs[kk][tx*8];
            float4 b1 = *(float4*)&Bs[kk][tx*8+4];
            float ar[8] = {a0.x,a0.y,a0.z,a0.w,a1.x,a1.y,a1.z,a1.w};
            float br[8] = {b0.x,b0.y,b0.z,b0.w,b1.x,b1.y,b1.z,b1.w};
#pragma unroll
            for (int i = 0; i < 8; i++)
#pragma unroll
                for (int j = 0; j < 8; j++)
                    acc[i][j] = fmaf(ar[i], br[j], acc[i][j]);
        }
        __syncthreads();
    }

#pragma unroll
    for (int i = 0; i < 8; i++) {
        const int r = row0 + ty*8 + i;
#pragma unroll
        for (int j = 0; j < 8; j++) {
            const int c = col0 + tx*8 + j;
            float v = acc[i][j] + bias[c];
            if (EPI == 1) v = geluf(v);
            if (EPI == 2) v = res[(size_t)r*256 + c] + geluf(v);
            out[(size_t)r*256 + c] = v;
        }
    }
}

// ---------------- LayerNorm over D=256, one warp per row ----------------
__global__ void __launch_bounds__(256)
ln_k(const float* __restrict__ x, const float* __restrict__ g,
     const float* __restrict__ bb, float* __restrict__ out, int Nr)
{
    const int warp = threadIdx.x >> 5, lane = threadIdx.x & 31;
    const int row = blockIdx.x * 8 + warp;
    if (row >= Nr) return;
    const float* xr = x + (size_t)row * 256;
    float v[8]; float s = 0.f;
#pragma unroll
    for (int j = 0; j < 8; j++) { v[j] = xr[lane + 32*j]; s += v[j]; }
#pragma unroll
    for (int o = 16; o; o >>= 1) s += __shfl_xor_sync(0xffffffffu, s, o);
    const float mu = s * (1.f/256.f);
    float q = 0.f;
#pragma unroll
    for (int j = 0; j < 8; j++) { float d = v[j] - mu; q += d*d; }
#pragma unroll
    for (int o = 16; o; o >>= 1) q += __shfl_xor_sync(0xffffffffu, q, o);
    const float rstd = rsqrtf(q * (1.f/256.f) + 1e-5f);
#pragma unroll
    for (int j = 0; j < 8; j++) {
        int c = lane + 32*j;
        out[(size_t)row*256 + c] = (v[j] - mu) * rstd * g[c] + bb[c];
    }
}

// ---------------- logits + Gumbel + argmax -> relation_id ----------------
// RNG stream (validated exactly by round-9 batch-0 split): JAX partitionable
// Threefry, key=(0,42), ctr=(hi,lo)=(0, flat_index), bits = x0 ^ x1.
__global__ void __launch_bounds__(256)
logits_k(const float* __restrict__ routed, const float* __restrict__ hp,
         int* __restrict__ rel)
{
    __shared__ float shp[2048];
    const int tid = threadIdx.x;
    for (int i = tid; i < 2048; i += 256) shp[i] = hp[i];
    __syncthreads();
    const int warp = tid >> 5, lane = tid & 31;
    const int ge = blockIdx.x * 8 + warp;
    const float* xr = routed + (size_t)ge * 256;
    float acc[8];
#pragma unroll
    for (int m = 0; m < 8; m++) acc[m] = 0.f;
#pragma unroll
    for (int j = 0; j < 8; j++) {
        float x = xr[lane + 32*j];
#pragma unroll
        for (int m = 0; m < 8; m++) acc[m] = fmaf(x, shp[m*256 + lane + 32*j], acc[m]);
    }
#pragma unroll
    for (int m = 0; m < 8; m++)
#pragma unroll
        for (int o = 16; o; o >>= 1) acc[m] += __shfl_xor_sync(0xffffffffu, acc[m], o);

    float pert = -3.4e38f; int mi = 31;
    if (lane < 8) {
        const unsigned i = (unsigned)ge * 8u + (unsigned)lane;  // flat (b,e,m) index
        unsigned x0 = 0u;   // counter hi word (flat index < 2^32)
        unsigned x1 = i;    // counter lo word
        threefry42(x0, x1);
        const unsigned bits = x0 ^ x1;     // XOR of both output words (stream E)
        float f = __uint_as_float((bits >> 9) | 0x3f800000u) - 1.0f;
        float u = f * (0.999999f - 1e-6f) + 1e-6f;
        u = fmaxf(u, 1e-6f);
        pert = acc[lane] - logf(-logf(u));
        mi = lane;
    }
#pragma unroll
    for (int o = 16; o; o >>= 1) {
        float op = __shfl_xor_sync(0xffffffffu, pert, o);
        int   om = __shfl_xor_sync(0xffffffffu, mi, o);
        if (op > pert || (op == pert && om < mi)) { pert = op; mi = om; }
    }
    if (lane == 0) rel[ge] = mi;
}

// ---------------- routing tail: capacity / guard / budget / pack ----------------
// One block per batch, 256 threads, 32 edges/thread. All sorts reduce to
// stable index order because edge_scores == 1.0 exactly (see analysis).
__global__ void __launch_bounds__(256)
tail_k(const int* __restrict__ eidx, float* __restrict__ dout)
{
    const int b = blockIdx.x, t = threadIdx.x;
    const int* relb = g_rel + b * E_;
    const int* srcb = eidx + b * 2 * E_;
    const int* dstb = srcb + E_;
    __shared__ int cnt[256][8];
    __shared__ int ccnt[256];
    __shared__ int cov[256];
    __shared__ int totKeep;
    const int base = t * 32;

    // --- capacity: rank within relation by index ---
#pragma unroll
    for (int j = 0; j < 8; j++) cnt[t][j] = 0;
    for (int i = 0; i < 32; i++) cnt[t][relb[base+i]]++;
    __syncthreads();
    if (t < 8) {
        int run = 0;
        for (int tt = 0; tt < 256; tt++) { int tmp = cnt[tt][t]; cnt[tt][t] = run; run += tmp; }
        atomicAdd(&g_cnt[2 + t], run);   // load histogram
    }
    __syncthreads();
    unsigned k1bits = 0; int c1 = 0;
    for (int i = 0; i < 32; i++) {
        int r = relb[base+i];
        int k1 = (cnt[t][r] < CAP_) ? 1 : 0;
        cnt[t][r]++;
        k1bits |= (unsigned)k1 << i; c1 += k1;
    }
    ccnt[t] = c1;
    __syncthreads();
    if (t == 0) { int s = 0; for (int tt = 0; tt < 256; tt++) s += ccnt[tt]; atomicAdd(&g_cnt[0], s); }
    cov[t] = 0;
    __syncthreads();

    // --- guard: nodes with no kept edge rescue all their edges ---
    for (int i = 0; i < 32; i++)
        if ((k1bits >> i) & 1u) { int e = base+i; cov[srcb[e]] = 1; cov[dstb[e]] = 1; }
    __syncthreads();
    unsigned k2bits = 0; int c2 = 0;
    for (int i = 0; i < 32; i++) {
        int e = base+i;
        int k2 = (int)((k1bits >> i) & 1u) | (cov[srcb[e]] == 0) | (cov[dstb[e]] == 0);
        k2bits |= (unsigned)k2 << i; c2 += k2;
    }
    __syncthreads();
    ccnt[t] = c2;
    __syncthreads();
    if (t == 0) { int run = 0; for (int tt = 0; tt < 256; tt++) { int tmp = ccnt[tt]; ccnt[tt] = run; run += tmp; } }
    __syncthreads();

    // --- budget: first BUDGET_ kept edges by index ---
    int rk = ccnt[t];
    unsigned k3bits = 0; int c3 = 0;
    for (int i = 0; i < 32; i++) {
        int k2 = (int)((k2bits >> i) & 1u);
        int k3 = k2 & ((rk < BUDGET_) ? 1 : 0);
        rk += k2;
        k3bits |= (unsigned)k3 << i; c3 += k3;
    }
    __syncthreads();
    ccnt[t] = c3;
    __syncthreads();
    if (t == 0) {
        int run = 0;
        for (int tt = 0; tt < 256; tt++) { int tmp = ccnt[tt]; ccnt[tt] = run; run += tmp; }
        totKeep = run; atomicAdd(&g_cnt[1], run);
    }
    __syncthreads();

    // --- pack (stable partition) + write outputs as float ---
    int nb = ccnt[t];
    const int Kb = totKeep;
    float* o_ti   = dout;
    float* o_rel  = dout + 65536;
    float* o_mask = dout + 98304;
    float* o_sc   = dout + 131072;
    for (int i = 0; i < 32; i++) {
        int e = base + i;
        int k3 = (int)((k3bits >> i) & 1u);
        int pos = k3 ? nb : (Kb + e - nb);
        nb += k3;
        o_ti[b*2*E_ + pos]      = (float)srcb[e];
        o_ti[b*2*E_ + E_ + pos] = (float)dstb[e];
        o_rel[b*E_ + pos]  = k3 ? (float)relb[e] : 0.f;
        o_mask[b*E_ + pos] = k3 ? 1.f : 0.f;
        o_sc[b*E_ + pos]   = k3 ? 1.f : 0.f;
    }
}

__global__ void zero_k() { if (threadIdx.x < 16) g_cnt[threadIdx.x] = 0; }

__global__ void fin_k(float* __restrict__ dout) {
    const int t = threadIdx.x;
    if (t < 8)  dout[163840 + t] = (float)g_cnt[2 + t] * (1.f / 32768.f);
    if (t == 8) dout[163848] = (float)g_cnt[1] * (1.f / 32768.f);
    if (t == 9) dout[163849] = 1.f - (float)g_cnt[0] * (1.f / 32768.f);
}

// ---------------- launch ----------------
extern "C" void kernel_launch(void* const* d_in, const int* in_sizes, int n_in,
                              void* d_out, int out_size)
{
    const float* node_x     = (const float*)d_in[0];
    const int*   edge_index = (const int*  )d_in[1];
    const float* edge_bank  = (const float*)d_in[2];
    const float* community  = (const float*)d_in[3];
    const float* W_node = (const float*)d_in[4];  const float* b_node = (const float*)d_in[5];
    const float* W_edge = (const float*)d_in[6];  const float* b_edge = (const float*)d_in[7];
    const float* W_comm = (const float*)d_in[8];  const float* b_comm = (const float*)d_in[9];
    const float* ln_c_g = (const float*)d_in[10]; const float* ln_c_b = (const float*)d_in[11];
    const float* W_clu  = (const float*)d_in[12]; const float* b_clu  = (const float*)d_in[13];
    const float* W_tok  = (const float*)d_in[14]; const float* b_tok  = (const float*)d_in[15];
    const float* W_r1   = (const float*)d_in[16]; const float* b_r1   = (const float*)d_in[17];
    const float* ln_r_g = (const float*)d_in[18]; const float* ln_r_b = (const float*)d_in[19];
    const float* W_r2   = (const float*)d_in[20]; const float* b_r2   = (const float*)d_in[21];
    const float* head_prompts = (const float*)d_in[22];
    float* out = (float*)d_out;

    float *p_node, *p_comm, *p_ef0, *p_buf1, *p_edge;
    int *p_rel;
    cudaGetSymbolAddress((void**)&p_node, g_node);
    cudaGetSymbolAddress((void**)&p_comm, g_comm);
    cudaGetSymbolAddress((void**)&p_ef0,  g_ef0);
    cudaGetSymbolAddress((void**)&p_buf1, g_buf1);
    cudaGetSymbolAddress((void**)&p_edge, g_edge);
    cudaGetSymbolAddress((void**)&p_rel,  g_rel);

    zero_k<<<1, 32>>>();

    // node_feat / comm_feat
    gemm_k<0,0><<<dim3(NR_/128, 2), 256>>>(node_x,   W_node, b_node, nullptr, p_node, 256, nullptr, nullptr, nullptr);
    gemm_k<0,0><<<dim3(NR_/128, 2), 256>>>(community, W_comm, b_comm, nullptr, p_comm, 32, nullptr, nullptr, nullptr);
    // edge_feat0
    gemm_k<0,0><<<dim3(NE_/128, 2), 256>>>(edge_bank, W_edge, b_edge, nullptr, p_ef0, 16, nullptr, nullptr, nullptr);
    // LN(edge_feat0)
    ln_k<<<NE_/8, 256>>>(p_ef0, ln_c_g, ln_c_b, p_buf1, NE_);
    // edge_feat = ef0 + gelu(lnE @ W_clu + b_clu)
    gemm_k<0,2><<<dim3(NE_/128, 2), 256>>>(p_buf1, W_clu, b_clu, p_ef0, p_edge, 256, nullptr, nullptr, nullptr);
    // token (K=1024, fused gather; domain_prompt rows of W_tok are dead)
    gemm_k<1,0><<<dim3(NE_/128, 2), 256>>>(p_edge, W_tok, b_tok, nullptr, p_ef0, 1024, p_node, p_comm, edge_index);
    // h = gelu(token @ W_r1 + b_r1)
    gemm_k<0,1><<<dim3(NE_/128, 2), 256>>>(p_ef0, W_r1, b_r1, nullptr, p_buf1, 256, nullptr, nullptr, nullptr);
    // lnH
    ln_k<<<NE_/8, 256>>>(p_buf1, ln_r_g, ln_r_b, p_edge, NE_);
    // routed = gelu(lnH @ W_r2 + b_r2)
    gemm_k<0,1><<<dim3(NE_/128, 2), 256>>>(p_edge, W_r2, b_r2, nullptr, p_ef0, 256, nullptr, nullptr, nullptr);
    // logits + gumbel + argmax
    logits_k<<<NE_/8, 256>>>(p_ef0, head_prompts, p_rel);
    // routing tail + pack + scalars
    tail_k<<<B_, 256>>>(edge_index, out);
    fin_k<<<1, 32>>>(out);
    (void)in_sizes; (void)n_in; (void)out_size;
}

// round 16
// speedup vs baseline: 1.1799x; 1.1799x over previous
#include <cuda_runtime.h>
#include <cstdint>
#include <cstddef>

#define B_ 4
#define R_ 256
#define E_ 8192
#define D_ 256
#define NE_ (B_*E_)   /* 32768 edge rows */
#define NR_ (B_*R_)   /* 1024 node rows */
#define CAP_ 1280
#define BUDGET_ 7864

// ---------------- static scratch (no allocs allowed) ----------------
__device__ float g_node[NR_*D_];     // node_feat
__device__ float g_comm[NR_*D_];     // comm_feat
__device__ float g_P2  [NR_*D_];     // node_feat @ W_tok[256:512)
__device__ float g_P3  [NR_*D_];     // node_feat @ W_tok[512:768)
__device__ float g_ef0 [NE_*D_];     // ef0 -> tok_part1 -> routed
__device__ float g_buf1[NE_*D_];     // lnE -> token -> lnH
__device__ float g_edge[NE_*D_];     // edge_feat -> h
__device__ float g_zero[D_];         // zero bias (zero-initialized .bss)
__device__ int   g_rel [NE_];
__device__ int   g_cnt [16];         // [0]=keep1 total, [1]=keep3 total, [2..9]=rel hist

// ---------------- helpers ----------------
__device__ __forceinline__ float geluf(float x) {
    return 0.5f * x * (1.0f + erff(x * 0.7071067811865476f));
}

// Threefry-2x32, key = (0, 42)  (jax.random.key(42))
__device__ __forceinline__ void threefry42(unsigned& x0, unsigned& x1) {
    const unsigned k0 = 0u, k1 = 42u;
    const unsigned k2 = k0 ^ k1 ^ 0x1BD11BDAu;
    x0 += k0; x1 += k1;
#define TF_RND(r) { x0 += x1; x1 = (x1 << (r)) | (x1 >> (32-(r))); x1 ^= x0; }
    TF_RND(13) TF_RND(15) TF_RND(26) TF_RND(6)   x0 += k1; x1 += k2 + 1u;
    TF_RND(17) TF_RND(29) TF_RND(16) TF_RND(24)  x0 += k2; x1 += k0 + 2u;
    TF_RND(13) TF_RND(15) TF_RND(26) TF_RND(6)   x0 += k0; x1 += k1 + 3u;
    TF_RND(17) TF_RND(29) TF_RND(16) TF_RND(24)  x0 += k1; x1 += k2 + 4u;
    TF_RND(13) TF_RND(15) TF_RND(26) TF_RND(6)   x0 += k2; x1 += k0 + 5u;
#undef TF_RND
}

// ---------------- GEMM: out[Nr x 256] = A[Nr x K] @ W[K x 256] (+epilogue) ----------------
// 128x128 block, BK=8, 256 threads, 8x8 per-thread microtile.
// AMODE: 0 = plain row-major A; 2 = |comm[src]-comm[dst]| gather loader (K=256).
// EPI:   0 = +bias; 1 = gelu(+bias); 2 = res + gelu(+bias);
//        3 = acc + res + P2[src] + P3[dst]   (token final; nodef=P2, A=P3, no bias)
template<int AMODE, int EPI>
__global__ void __launch_bounds__(256, 2)
gemm_k(const float* __restrict__ A, const float* __restrict__ W,
       const float* __restrict__ bias, const float* __restrict__ res,
       float* __restrict__ out, int K,
       const float* __restrict__ nodef, const float* __restrict__ commf,
       const int* __restrict__ eidx)
{
    __shared__ float As[8][128];
    __shared__ float Bs[8][128];
    const int tid = threadIdx.x;
    const int tx = tid & 15, ty = tid >> 4;
    const int row0 = blockIdx.x * 128;
    const int col0 = blockIdx.y * 128;

    const int arow = tid >> 1;            // 0..127
    const int akk0 = (tid & 1) * 4;       // 0 or 4
    const int bkk  = tid >> 5;            // 0..7
    const int bcol = (tid << 2) & 127;    // 0..124 step 4

    float acc[8][8];
#pragma unroll
    for (int i = 0; i < 8; i++)
#pragma unroll
        for (int j = 0; j < 8; j++) acc[i][j] = 0.f;

    for (int k0 = 0; k0 < K; k0 += 8) {
        float4 av;
        const int grow = row0 + arow;
        if (AMODE == 0) {
            av = *(const float4*)(A + (size_t)grow*K + k0 + akk0);
        } else {
            int b = grow >> 13, e = grow & 8191;
            int s = eidx[b*2*E_ + e];
            int d = eidx[b*2*E_ + E_ + e];
            int rb = b * R_;
            float4 a = *(const float4*)(commf + (size_t)(rb+s)*256 + k0 + akk0);
            float4 c = *(const float4*)(commf + (size_t)(rb+d)*256 + k0 + akk0);
            av = make_float4(fabsf(a.x-c.x), fabsf(a.y-c.y), fabsf(a.z-c.z), fabsf(a.w-c.w));
        }
        As[akk0+0][arow] = av.x; As[akk0+1][arow] = av.y;
        As[akk0+2][arow] = av.z; As[akk0+3][arow] = av.w;

        float4 bv = *(const float4*)(W + (size_t)(k0+bkk)*256 + col0 + bcol);
        *(float4*)&Bs[bkk][bcol] = bv;
        __syncthreads();

#pragma unroll
        for (int kk = 0; kk < 8; kk++) {
            float4 a0 = *(float4*)&As[kk][ty*8];
            float4 a1 = *(float4*)&As[kk][ty*8+4];
            float4 b0 = *(float4*)&Bs[kk][tx*8];
            float4 b1 = *(float4*)&Bs[kk][tx*8+4];
            float ar[8] = {a0.x,a0.y,a0.z,a0.w,a1.x,a1.y,a1.z,a1.w};
            float br[8] = {b0.x,b0.y,b0.z,b0.w,b1.x,b1.y,b1.z,b1.w};
#pragma unroll
            for (int i = 0; i < 8; i++)
#pragma unroll
                for (int j = 0; j < 8; j++)
                    acc[i][j] = fmaf(ar[i], br[j], acc[i][j]);
        }
        __syncthreads();
    }

#pragma unroll
    for (int i = 0; i < 8; i++) {
        const int r = row0 + ty*8 + i;
        int s = 0, d = 0, rb = 0;
        if (EPI == 3) {
            int b = r >> 13, e = r & 8191;
            s = eidx[b*2*E_ + e];
            d = eidx[b*2*E_ + E_ + e];
            rb = b * R_;
        }
#pragma unroll
        for (int j = 0; j < 8; j++) {
            const int c = col0 + tx*8 + j;
            float v;
            if (EPI == 3) {
                v = acc[i][j] + res[(size_t)r*256 + c]
                  + nodef[(size_t)(rb+s)*256 + c]   // P2[src]
                  + A    [(size_t)(rb+d)*256 + c];  // P3[dst] (A param reused)
            } else {
                v = acc[i][j] + bias[c];
                if (EPI == 1) v = geluf(v);
                if (EPI == 2) v = res[(size_t)r*256 + c] + geluf(v);
            }
            out[(size_t)r*256 + c] = v;
        }
    }
}

// ---------------- batched pair of small GEMMs (node-level, 1024 rows) ----------------
struct SJob { const float* A; const float* W; const float* bias; float* out; int K; };

__global__ void __launch_bounds__(256, 2)
small2_k(SJob j0, SJob j1)
{
    const SJob jb = blockIdx.z ? j1 : j0;
    const float* __restrict__ A = jb.A;
    const float* __restrict__ W = jb.W;
    const float* __restrict__ bias = jb.bias;
    float* __restrict__ out = jb.out;
    const int K = jb.K;

    __shared__ float As[8][128];
    __shared__ float Bs[8][128];
    const int tid = threadIdx.x;
    const int tx = tid & 15, ty = tid >> 4;
    const int row0 = blockIdx.x * 128;
    const int col0 = blockIdx.y * 128;
    const int arow = tid >> 1;
    const int akk0 = (tid & 1) * 4;
    const int bkk  = tid >> 5;
    const int bcol = (tid << 2) & 127;

    float acc[8][8];
#pragma unroll
    for (int i = 0; i < 8; i++)
#pragma unroll
        for (int j = 0; j < 8; j++) acc[i][j] = 0.f;

    for (int k0 = 0; k0 < K; k0 += 8) {
        const int grow = row0 + arow;
        float4 av = *(const float4*)(A + (size_t)grow*K + k0 + akk0);
        As[akk0+0][arow] = av.x; As[akk0+1][arow] = av.y;
        As[akk0+2][arow] = av.z; As[akk0+3][arow] = av.w;
        float4 bv = *(const float4*)(W + (size_t)(k0+bkk)*256 + col0 + bcol);
        *(float4*)&Bs[bkk][bcol] = bv;
        __syncthreads();
#pragma unroll
        for (int kk = 0; kk < 8; kk++) {
            float4 a0 = *(float4*)&As[kk][ty*8];
            float4 a1 = *(float4*)&As[kk][ty*8+4];
            float4 b0 = *(float4*)&Bs[kk][tx*8];
            float4 b1 = *(float4*)&Bs[kk][tx*8+4];
            float ar[8] = {a0.x,a0.y,a0.z,a0.w,a1.x,a1.y,a1.z,a1.w};
            float br[8] = {b0.x,b0.y,b0.z,b0.w,b1.x,b1.y,b1.z,b1.w};
#pragma unroll
            for (int i = 0; i < 8; i++)
#pragma unroll
                for (int j = 0; j < 8; j++)
                    acc[i][j] = fmaf(ar[i], br[j], acc[i][j]);
        }
        __syncthreads();
    }
#pragma unroll
    for (int i = 0; i < 8; i++) {
        const int r = row0 + ty*8 + i;
#pragma unroll
        for (int j = 0; j < 8; j++) {
            const int c = col0 + tx*8 + j;
            out[(size_t)r*256 + c] = acc[i][j] + bias[c];
        }
    }
}

// ---------------- fused ef0 GEMM (K=16) + LayerNorm ----------------
// One warp per edge row: ef0 = edge_bank_row @ W_edge + b_edge; lnE = LN(ef0).
// Writes ef0 -> g_ef0, lnE -> g_buf1. W_edge (16x256) cached in smem.
__global__ void __launch_bounds__(256)
edgeln_k(const float* __restrict__ ebank, const float* __restrict__ Wf,
         const float* __restrict__ bf,
         const float* __restrict__ g, const float* __restrict__ bb,
         float* __restrict__ ef0, float* __restrict__ lne)
{
    __shared__ float Ws[16*256];
    const int tid = threadIdx.x;
    for (int i = tid*4; i < 16*256; i += 256*4)
        *(float4*)&Ws[i] = *(const float4*)(Wf + i);
    __syncthreads();

    const int warp = tid >> 5, lane = tid & 31;
    const int wg = blockIdx.x * 8 + warp;          // 0..4095
    for (int it = 0; it < 8; it++) {
        const int row = wg + it * 4096;            // 0..32767
        float aval = (lane < 16) ? ebank[(size_t)row*16 + lane] : 0.f;
        float v[8];
#pragma unroll
        for (int j = 0; j < 8; j++) {
            const int c = lane + 32*j;
            float s = bf[c];
#pragma unroll
            for (int k = 0; k < 16; k++)
                s = fmaf(__shfl_sync(0xffffffffu, aval, k), Ws[k*256 + c], s);
            v[j] = s;
            ef0[(size_t)row*256 + c] = s;
        }
        // LayerNorm (same op order as ln_k)
        float s = 0.f;
#pragma unroll
        for (int j = 0; j < 8; j++) s += v[j];
#pragma unroll
        for (int o = 16; o; o >>= 1) s += __shfl_xor_sync(0xffffffffu, s, o);
        const float mu = s * (1.f/256.f);
        float q = 0.f;
#pragma unroll
        for (int j = 0; j < 8; j++) { float dd = v[j] - mu; q += dd*dd; }
#pragma unroll
        for (int o = 16; o; o >>= 1) q += __shfl_xor_sync(0xffffffffu, q, o);
        const float rstd = rsqrtf(q * (1.f/256.f) + 1e-5f);
#pragma unroll
        for (int j = 0; j < 8; j++) {
            const int c = lane + 32*j;
            lne[(size_t)row*256 + c] = (v[j] - mu) * rstd * g[c] + bb[c];
        }
    }
}

// ---------------- LayerNorm over D=256, one warp per row ----------------
__global__ void __launch_bounds__(256)
ln_k(const float* __restrict__ x, const float* __restrict__ g,
     const float* __restrict__ bb, float* __restrict__ out, int Nr)
{
    const int warp = threadIdx.x >> 5, lane = threadIdx.x & 31;
    const int row = blockIdx.x * 8 + warp;
    if (row >= Nr) return;
    const float* xr = x + (size_t)row * 256;
    float v[8]; float s = 0.f;
#pragma unroll
    for (int j = 0; j < 8; j++) { v[j] = xr[lane + 32*j]; s += v[j]; }
#pragma unroll
    for (int o = 16; o; o >>= 1) s += __shfl_xor_sync(0xffffffffu, s, o);
    const float mu = s * (1.f/256.f);
    float q = 0.f;
#pragma unroll
    for (int j = 0; j < 8; j++) { float d = v[j] - mu; q += d*d; }
#pragma unroll
    for (int o = 16; o; o >>= 1) q += __shfl_xor_sync(0xffffffffu, q, o);
    const float rstd = rsqrtf(q * (1.f/256.f) + 1e-5f);
#pragma unroll
    for (int j = 0; j < 8; j++) {
        int c = lane + 32*j;
        out[(size_t)row*256 + c] = (v[j] - mu) * rstd * g[c] + bb[c];
    }
}

// ---------------- logits + Gumbel + argmax -> relation_id ----------------
// RNG stream (validated exactly): JAX partitionable Threefry, key=(0,42),
// ctr=(hi,lo)=(0, flat_index), bits = x0 ^ x1.
__global__ void __launch_bounds__(256)
logits_k(const float* __restrict__ routed, const float* __restrict__ hp,
         int* __restrict__ rel)
{
    __shared__ float shp[2048];
    const int tid = threadIdx.x;
    for (int i = tid; i < 2048; i += 256) shp[i] = hp[i];
    __syncthreads();
    const int warp = tid >> 5, lane = tid & 31;
    const int ge = blockIdx.x * 8 + warp;
    const float* xr = routed + (size_t)ge * 256;
    float acc[8];
#pragma unroll
    for (int m = 0; m < 8; m++) acc[m] = 0.f;
#pragma unroll
    for (int j = 0; j < 8; j++) {
        float x = xr[lane + 32*j];
#pragma unroll
        for (int m = 0; m < 8; m++) acc[m] = fmaf(x, shp[m*256 + lane + 32*j], acc[m]);
    }
#pragma unroll
    for (int m = 0; m < 8; m++)
#pragma unroll
        for (int o = 16; o; o >>= 1) acc[m] += __shfl_xor_sync(0xffffffffu, acc[m], o);

    float pert = -3.4e38f; int mi = 31;
    if (lane < 8) {
        const unsigned i = (unsigned)ge * 8u + (unsigned)lane;  // flat (b,e,m) index
        unsigned x0 = 0u;   // counter hi word
        unsigned x1 = i;    // counter lo word
        threefry42(x0, x1);
        const unsigned bits = x0 ^ x1;     // XOR of both output words (stream E)
        float f = __uint_as_float((bits >> 9) | 0x3f800000u) - 1.0f;
        float u = f * (0.999999f - 1e-6f) + 1e-6f;
        u = fmaxf(u, 1e-6f);
        pert = acc[lane] - logf(-logf(u));
        mi = lane;
    }
#pragma unroll
    for (int o = 16; o; o >>= 1) {
        float op = __shfl_xor_sync(0xffffffffu, pert, o);
        int   om = __shfl_xor_sync(0xffffffffu, mi, o);
        if (op > pert || (op == pert && om < mi)) { pert = op; mi = om; }
    }
    if (lane == 0) rel[ge] = mi;
}

// ---------------- routing tail: capacity / guard / budget / pack ----------------
__global__ void __launch_bounds__(256)
tail_k(const int* __restrict__ eidx, float* __restrict__ dout)
{
    const int b = blockIdx.x, t = threadIdx.x;
    const int* relb = g_rel + b * E_;
    const int* srcb = eidx + b * 2 * E_;
    const int* dstb = srcb + E_;
    __shared__ int cnt[256][8];
    __shared__ int ccnt[256];
    __shared__ int cov[256];
    __shared__ int totKeep;
    const int base = t * 32;

    // --- capacity: rank within relation by index ---
#pragma unroll
    for (int j = 0; j < 8; j++) cnt[t][j] = 0;
    for (int i = 0; i < 32; i++) cnt[t][relb[base+i]]++;
    __syncthreads();
    if (t < 8) {
        int run = 0;
        for (int tt = 0; tt < 256; tt++) { int tmp = cnt[tt][t]; cnt[tt][t] = run; run += tmp; }
        atomicAdd(&g_cnt[2 + t], run);   // load histogram
    }
    __syncthreads();
    unsigned k1bits = 0; int c1 = 0;
    for (int i = 0; i < 32; i++) {
        int r = relb[base+i];
        int k1 = (cnt[t][r] < CAP_) ? 1 : 0;
        cnt[t][r]++;
        k1bits |= (unsigned)k1 << i; c1 += k1;
    }
    ccnt[t] = c1;
    __syncthreads();
    if (t == 0) { int s = 0; for (int tt = 0; tt < 256; tt++) s += ccnt[tt]; atomicAdd(&g_cnt[0], s); }
    cov[t] = 0;
    __syncthreads();

    // --- guard ---
    for (int i = 0; i < 32; i++)
        if ((k1bits >> i) & 1u) { int e = base+i; cov[srcb[e]] = 1; cov[dstb[e]] = 1; }
    __syncthreads();
    unsigned k2bits = 0; int c2 = 0;
    for (int i = 0; i < 32; i++) {
        int e = base+i;
        int k2 = (int)((k1bits >> i) & 1u) | (cov[srcb[e]] == 0) | (cov[dstb[e]] == 0);
        k2bits |= (unsigned)k2 << i; c2 += k2;
    }
    __syncthreads();
    ccnt[t] = c2;
    __syncthreads();
    if (t == 0) { int run = 0; for (int tt = 0; tt < 256; tt++) { int tmp = ccnt[tt]; ccnt[tt] = run; run += tmp; } }
    __syncthreads();

    // --- budget ---
    int rk = ccnt[t];
    unsigned k3bits = 0; int c3 = 0;
    for (int i = 0; i < 32; i++) {
        int k2 = (int)((k2bits >> i) & 1u);
        int k3 = k2 & ((rk < BUDGET_) ? 1 : 0);
        rk += k2;
        k3bits |= (unsigned)k3 << i; c3 += k3;
    }
    __syncthreads();
    ccnt[t] = c3;
    __syncthreads();
    if (t == 0) {
        int run = 0;
        for (int tt = 0; tt < 256; tt++) { int tmp = ccnt[tt]; ccnt[tt] = run; run += tmp; }
        totKeep = run; atomicAdd(&g_cnt[1], run);
    }
    __syncthreads();

    // --- pack ---
    int nb = ccnt[t];
    const int Kb = totKeep;
    float* o_ti   = dout;
    float* o_rel  = dout + 65536;
    float* o_mask = dout + 98304;
    float* o_sc   = dout + 131072;
    for (int i = 0; i < 32; i++) {
        int e = base + i;
        int k3 = (int)((k3bits >> i) & 1u);
        int pos = k3 ? nb : (Kb + e - nb);
        nb += k3;
        o_ti[b*2*E_ + pos]      = (float)srcb[e];
        o_ti[b*2*E_ + E_ + pos] = (float)dstb[e];
        o_rel[b*E_ + pos]  = k3 ? (float)relb[e] : 0.f;
        o_mask[b*E_ + pos] = k3 ? 1.f : 0.f;
        o_sc[b*E_ + pos]   = k3 ? 1.f : 0.f;
    }
}

__global__ void zero_k() { if (threadIdx.x < 16) g_cnt[threadIdx.x] = 0; }

__global__ void fin_k(float* __restrict__ dout) {
    const int t = threadIdx.x;
    if (t < 8)  dout[163840 + t] = (float)g_cnt[2 + t] * (1.f / 32768.f);
    if (t == 8) dout[163848] = (float)g_cnt[1] * (1.f / 32768.f);
    if (t == 9) dout[163849] = 1.f - (float)g_cnt[0] * (1.f / 32768.f);
}

// ---------------- launch ----------------
extern "C" void kernel_launch(void* const* d_in, const int* in_sizes, int n_in,
                              void* d_out, int out_size)
{
    const float* node_x     = (const float*)d_in[0];
    const int*   edge_index = (const int*  )d_in[1];
    const float* edge_bank  = (const float*)d_in[2];
    const float* community  = (const float*)d_in[3];
    const float* W_node = (const float*)d_in[4];  const float* b_node = (const float*)d_in[5];
    const float* W_edge = (const float*)d_in[6];  const float* b_edge = (const float*)d_in[7];
    const float* W_comm = (const float*)d_in[8];  const float* b_comm = (const float*)d_in[9];
    const float* ln_c_g = (const float*)d_in[10]; const float* ln_c_b = (const float*)d_in[11];
    const float* W_clu  = (const float*)d_in[12]; const float* b_clu  = (const float*)d_in[13];
    const float* W_tok  = (const float*)d_in[14]; const float* b_tok  = (const float*)d_in[15];
    const float* W_r1   = (const float*)d_in[16]; const float* b_r1   = (const float*)d_in[17];
    const float* ln_r_g = (const float*)d_in[18]; const float* ln_r_b = (const float*)d_in[19];
    const float* W_r2   = (const float*)d_in[20]; const float* b_r2   = (const float*)d_in[21];
    const float* head_prompts = (const float*)d_in[22];
    float* out = (float*)d_out;

    float *p_node, *p_comm, *p_P2, *p_P3, *p_ef0, *p_buf1, *p_edge, *p_zero;
    int *p_rel;
    cudaGetSymbolAddress((void**)&p_node, g_node);
    cudaGetSymbolAddress((void**)&p_comm, g_comm);
    cudaGetSymbolAddress((void**)&p_P2,   g_P2);
    cudaGetSymbolAddress((void**)&p_P3,   g_P3);
    cudaGetSymbolAddress((void**)&p_ef0,  g_ef0);
    cudaGetSymbolAddress((void**)&p_buf1, g_buf1);
    cudaGetSymbolAddress((void**)&p_edge, g_edge);
    cudaGetSymbolAddress((void**)&p_zero, g_zero);
    cudaGetSymbolAddress((void**)&p_rel,  g_rel);

    // W_tok row slices (token input layout: [edge | src | dst | comm | dead])
    const float* Wt_edge = W_tok;              // rows [0,256)
    const float* Wt_src  = W_tok + 256*256;    // rows [256,512)
    const float* Wt_dst  = W_tok + 512*256;    // rows [512,768)
    const float* Wt_cm   = W_tok + 768*256;    // rows [768,1024)

    zero_k<<<1, 32>>>();

    // node_feat + comm_feat (batched)
    {
        SJob j0{node_x,    W_node, b_node, p_node, 256};
        SJob j1{community, W_comm, b_comm, p_comm, 32};
        small2_k<<<dim3(NR_/128, 2, 2), 256>>>(j0, j1);
    }
    // P2 = node_feat @ Wt_src ; P3 = node_feat @ Wt_dst (batched)
    {
        SJob j0{p_node, Wt_src, p_zero, p_P2, 256};
        SJob j1{p_node, Wt_dst, p_zero, p_P3, 256};
        small2_k<<<dim3(NR_/128, 2, 2), 256>>>(j0, j1);
    }
    // ef0 (K=16 GEMM) + LN fused -> g_ef0, g_buf1
    edgeln_k<<<512, 256>>>(edge_bank, W_edge, b_edge, ln_c_g, ln_c_b, p_ef0, p_buf1);
    // edge_feat = ef0 + gelu(lnE @ W_clu + b_clu)
    gemm_k<0,2><<<dim3(NE_/128, 2), 256>>>(p_buf1, W_clu, b_clu, p_ef0, p_edge, 256, nullptr, nullptr, nullptr);
    // tok_part1 = edge_feat @ Wt_edge + b_tok
    gemm_k<0,0><<<dim3(NE_/128, 2), 256>>>(p_edge, Wt_edge, b_tok, nullptr, p_ef0, 256, nullptr, nullptr, nullptr);
    // token = |dcomm| @ Wt_cm + tok_part1 + P2[src] + P3[dst]
    gemm_k<2,3><<<dim3(NE_/128, 2), 256>>>(p_P3, Wt_cm, p_zero, p_ef0, p_buf1, 256, p_P2, p_comm, edge_index);
    // h = gelu(token @ W_r1 + b_r1)
    gemm_k<0,1><<<dim3(NE_/128, 2), 256>>>(p_buf1, W_r1, b_r1, nullptr, p_edge, 256, nullptr, nullptr, nullptr);
    // lnH
    ln_k<<<NE_/8, 256>>>(p_edge, ln_r_g, ln_r_b, p_buf1, NE_);
    // routed = gelu(lnH @ W_r2 + b_r2)
    gemm_k<0,1><<<dim3(NE_/128, 2), 256>>>(p_buf1, W_r2, b_r2, nullptr, p_ef0, 256, nullptr, nullptr, nullptr);
    // logits + gumbel + argmax
    logits_k<<<NE_/8, 256>>>(p_ef0, head_prompts, p_rel);
    // routing tail + pack + scalars
    tail_k<<<B_, 256>>>(edge_index, out);
    fin_k<<<1, 32>>>(out);
    (void)in_sizes; (void)n_in; (void)out_size;
}